// round 1
// baseline (speedup 1.0000x reference)
#include <cuda_runtime.h>
#include <climits>

// Problem constants (fixed by reference setup_inputs)
#define H      4096
#define W      4096
#define CHOFF  (4096 * 4096)
#define NT     31          // ceil((4096-256)/128)+1
#define TILE   256
#define STRIDE 128

// Global bbox accumulator: {ymin, ymax, xmin, xmax}
__device__ int dbox[4];

__global__ void init_kernel() {
    dbox[0] = INT_MAX;  // ymin
    dbox[1] = -1;       // ymax
    dbox[2] = INT_MAX;  // xmin
    dbox[3] = -1;       // xmax
}

// One block per tile, one thread per tile column.
// Computes E = sobel_y * (gauss * gray_tile) with per-tile zero padding,
// finds the bbox of {E != 0} via early-exit top/bottom row scans,
// expands by +-2 (the 5x5 dilation), clips to the tile, atomically merges.
__global__ __launch_bounds__(256) void tile_kernel(
    const float* __restrict__ x,
    const float* __restrict__ gw,
    const float* __restrict__ gauss,
    const float* __restrict__ sobel)
{
    __shared__ float grow[7][260];   // gray rows i-3..i+3, col halo +-2 (zero pad)
    __shared__ float brow[3][258];   // blurred rows i-1..i+1, col halo +-1 (zero pad)
    __shared__ int sF[8], sL[8], sMn[8], sMx[8];

    const int tid = threadIdx.x;
    const int ty  = blockIdx.x / NT;
    const int tx  = blockIdx.x % NT;
    const int y0  = ty * STRIDE;
    const int x0  = tx * STRIDE;

    const float w0 = gw[0], w1 = gw[1], w2 = gw[2];
    float gk[25];
    #pragma unroll
    for (int t = 0; t < 25; ++t) gk[t] = gauss[t];
    float sk[9];
    #pragma unroll
    for (int t = 0; t < 9; ++t) sk[t] = sobel[t];

    // Static zero halos (outside-tile zero padding; never overwritten)
    if (tid < 2) {
        #pragma unroll
        for (int rr = 0; rr < 7; ++rr) {
            grow[rr][tid]       = 0.f;
            grow[rr][258 + tid] = 0.f;
        }
    }
    if (tid == 0) {
        brow[0][0] = brow[1][0] = brow[2][0] = 0.f;
        brow[0][257] = brow[1][257] = brow[2][257] = 0.f;
    }

    // Compute one row i of E (sobel-of-gauss) for this thread's column.
    // Per-tile zero padding: gray outside [0,256)^2 is 0; blurred rows/cols
    // outside [0,256) are 0 (sobel pads the *blurred* tensor).
    auto compute_row = [&](int i) -> float {
        // Load gray rows i-3..i+3 (fused gray = w . x over channels)
        for (int rr = 0; rr < 7; ++rr) {
            int r = i - 3 + rr;
            float v = 0.f;
            if ((unsigned)r < 256u) {
                int off = (y0 + r) * W + (x0 + tid);
                v = w0 * x[off] + w1 * x[off + CHOFF] + w2 * x[off + 2 * CHOFF];
            }
            grow[rr][2 + tid] = v;
        }
        __syncthreads();
        // Blurred rows i-1..i+1 (5x5 gauss, cross-correlation, zero-pad gray)
        #pragma unroll
        for (int k = 0; k < 3; ++k) {
            int r = i - 1 + k;
            float b = 0.f;
            if ((unsigned)r < 256u) {
                #pragma unroll
                for (int a = 0; a < 5; ++a)
                    #pragma unroll
                    for (int c = 0; c < 5; ++c)
                        b += gk[a * 5 + c] * grow[k + a][tid + c];
            }
            brow[k][1 + tid] = b;
        }
        __syncthreads();
        // E row i (3x3 sobel over blurred, zero-pad blurred)
        float e = 0.f;
        #pragma unroll
        for (int a = 0; a < 3; ++a)
            #pragma unroll
            for (int c = 0; c < 3; ++c)
                e += sk[a * 3 + c] * brow[a][tid + c];
        return e;
        // NOTE: callers follow with __syncthreads_count, which also fences the
        // smem reuse across iterations.
    };

    bool has = false;
    int firstRow = 0, lastRow = -1;
    int T_stop = -1;
    bool exhausted = true;

    // Top scan: until every column has found a nonzero (or rows exhausted)
    for (int i = 0; i < 256; ++i) {
        float e = compute_row(i);
        if (e != 0.f) {
            if (!has) { has = true; firstRow = i; }
            lastRow = i;
        }
        if (__syncthreads_count(has ? 0 : 1) == 0) {
            T_stop = i;
            exhausted = false;
            break;
        }
    }

    // Bottom scan (only if top scan exited early => every column has a nonzero)
    if (!exhausted && T_stop < 255) {
        bool bot = false;
        for (int i = 255; i > T_stop; --i) {
            float e = compute_row(i);
            if (e != 0.f) {
                bot = true;
                if (i > lastRow) lastRow = i;
            }
            if (__syncthreads_count(bot ? 0 : 1) == 0) break;
        }
    }

    // Block reduction: min first row, max last row, min/max column with any hit
    int vF  = has ? firstRow : INT_MAX;
    int vL  = lastRow;                 // -1 if !has
    int vMn = has ? tid : INT_MAX;
    int vMx = has ? tid : -1;
    const unsigned FULL = 0xffffffffu;
    vF  = __reduce_min_sync(FULL, vF);
    vL  = __reduce_max_sync(FULL, vL);
    vMn = __reduce_min_sync(FULL, vMn);
    vMx = __reduce_max_sync(FULL, vMx);
    int wid = tid >> 5, lane = tid & 31;
    if (lane == 0) { sF[wid] = vF; sL[wid] = vL; sMn[wid] = vMn; sMx[wid] = vMx; }
    __syncthreads();
    if (tid == 0) {
        int f = INT_MAX, l = -1, mn = INT_MAX, mx = -1;
        #pragma unroll
        for (int k = 0; k < 8; ++k) {
            f  = min(f,  sF[k]);
            l  = max(l,  sL[k]);
            mn = min(mn, sMn[k]);
            mx = max(mx, sMx[k]);
        }
        if (l >= 0) {
            // 5x5 dilation: expand bbox by +-2, clip to tile, map to global
            atomicMin(&dbox[0], y0 + max(0,   f  - 2));
            atomicMax(&dbox[1], y0 + min(255, l  + 2));
            atomicMin(&dbox[2], x0 + max(0,   mn - 2));
            atomicMax(&dbox[3], x0 + min(255, mx + 2));
        }
    }
}

__global__ void fin_kernel(float* __restrict__ out) {
    if (dbox[1] < 0) {
        out[0] = 0.f; out[1] = 0.f; out[2] = 0.f; out[3] = 0.f;
    } else {
        out[0] = (float)dbox[2];        // x_min
        out[1] = (float)dbox[0];        // y_min
        out[2] = (float)(dbox[3] + 1);  // x_max
        out[3] = (float)(dbox[1] + 1);  // y_max
    }
}

extern "C" void kernel_launch(void* const* d_in, const int* in_sizes, int n_in,
                              void* d_out, int out_size)
{
    const float* x     = (const float*)d_in[0];
    const float* gw    = (const float*)d_in[1];
    const float* gauss = (const float*)d_in[2];
    const float* sobel = (const float*)d_in[3];

    init_kernel<<<1, 1>>>();
    tile_kernel<<<NT * NT, 256>>>(x, gw, gauss, sobel);
    fin_kernel<<<1, 1>>>((float*)d_out);
}

// round 2
// speedup vs baseline: 1.2187x; 1.2187x over previous
#include <cuda_runtime.h>
#include <climits>

// Problem constants (fixed by reference setup_inputs)
#define W       4096
#define CHOFF   (4096 * 4096)
#define NT      31          // ceil((4096-256)/128)+1
#define STRIDE  128
#define NBLOCKS (NT * NT)   // 961

// Encoded bbox accumulators, all atomicMax with init 0:
//  dstate[0] = max(ymax+1)       in [1,4096]
//  dstate[1] = max(4096 - ymin)  in [1,4096]
//  dstate[2] = max(xmax+1)
//  dstate[3] = max(4096 - xmin)
//  dstate[4] = completion counter
__device__ int dstate[5];

__global__ __launch_bounds__(256) void tile_kernel(
    const float* __restrict__ x,
    const float* __restrict__ gw,
    const float* __restrict__ gauss,
    const float* __restrict__ sobel,
    float* __restrict__ out)
{
    __shared__ float g[8][260];   // gray rows, col halo +-2 (zero pad)
    __shared__ float b[4][258];   // blurred rows, col halo +-1 (zero pad)
    __shared__ int sF[8], sL[8], sMn[8], sMx[8];

    const int tid = threadIdx.x;
    const int ty  = blockIdx.x / NT;
    const int tx  = blockIdx.x % NT;
    const int y0  = ty * STRIDE;
    const int x0  = tx * STRIDE;

    const float w0 = gw[0], w1 = gw[1], w2 = gw[2];
    float gk[25];
    #pragma unroll
    for (int t = 0; t < 25; ++t) gk[t] = gauss[t];
    float sk[9];
    #pragma unroll
    for (int t = 0; t < 9; ++t) sk[t] = sobel[t];

    // Static zero halos (outside-tile zero padding; never overwritten)
    if (tid < 2) {
        #pragma unroll
        for (int rr = 0; rr < 8; ++rr) {
            g[rr][tid]       = 0.f;
            g[rr][258 + tid] = 0.f;
        }
    }
    if (tid == 0) {
        #pragma unroll
        for (int k = 0; k < 4; ++k) { b[k][0] = 0.f; b[k][257] = 0.f; }
    }

    // ---------------- FAST PATH ----------------
    // E(0) depends on blurred rows 0,1 -> gray rows 0..3.
    // E(255) depends on blurred rows 254,255 -> gray rows 252..255.
    // Load all 8 gray rows in one unrolled batch (24 independent LDGs).
    #pragma unroll
    for (int rr = 0; rr < 8; ++rr) {
        int r = (rr < 4) ? rr : 248 + rr;           // 0..3, 252..255
        int off = (y0 + r) * W + (x0 + tid);
        g[rr][2 + tid] = w0 * x[off] + w1 * x[off + CHOFF] + w2 * x[off + 2 * CHOFF];
    }
    __syncthreads();

    // Blurred rows 0, 1, 254, 255 (5x5 gauss, zero-pad gray rows outside tile)
    {
        float b0 = 0.f, b1 = 0.f, b254 = 0.f, b255 = 0.f;
        #pragma unroll
        for (int a = 0; a < 5; ++a) {
            #pragma unroll
            for (int c = 0; c < 5; ++c) {
                float k = gk[a * 5 + c];
                if (a >= 2) b0   += k * g[a - 2][tid + c];   // gray rows -2..2 -> 0..2
                if (a >= 1) b1   += k * g[a - 1][tid + c];   // gray rows -1..3 -> 0..3
                if (a <  4) b254 += k * g[4 + a][tid + c];   // gray rows 252..256 -> 252..255
                if (a <  3) b255 += k * g[5 + a][tid + c];   // gray rows 253..257 -> 253..255
            }
        }
        b[0][1 + tid] = b0;
        b[1][1 + tid] = b1;
        b[2][1 + tid] = b254;
        b[3][1 + tid] = b255;
    }
    __syncthreads();

    // E(0): sobel rows over blurred(-1)=0, blurred(0), blurred(1)
    // E(255): blurred(254), blurred(255), blurred(256)=0
    float e0 = 0.f, e255 = 0.f;
    #pragma unroll
    for (int c = 0; c < 3; ++c) {
        e0   += sk[3 + c] * b[0][tid + c] + sk[6 + c] * b[1][tid + c];
        e255 += sk[c]     * b[2][tid + c] + sk[3 + c] * b[3][tid + c];
    }
    int miss = (e0 == 0.f) || (e255 == 0.f);
    bool fast = (__syncthreads_count(miss) == 0);

    if (fast) {
        // Every column has a nonzero edge on rows 0 and 255 -> bbox of
        // {E!=0} = full tile; +-2 dilation clipped to tile = full tile.
        if (tid == 0) {
            atomicMax(&dstate[0], y0 + 256);
            atomicMax(&dstate[1], 4096 - y0);
            atomicMax(&dstate[2], x0 + 256);
            atomicMax(&dstate[3], 4096 - x0);
        }
    } else {
        // ---------------- GENERIC FALLBACK (rare/never) ----------------
        auto compute_row = [&](int i) -> float {
            for (int rr = 0; rr < 7; ++rr) {
                int r = i - 3 + rr;
                float v = 0.f;
                if ((unsigned)r < 256u) {
                    int off = (y0 + r) * W + (x0 + tid);
                    v = w0 * x[off] + w1 * x[off + CHOFF] + w2 * x[off + 2 * CHOFF];
                }
                g[rr][2 + tid] = v;
            }
            __syncthreads();
            #pragma unroll
            for (int k = 0; k < 3; ++k) {
                int r = i - 1 + k;
                float bb = 0.f;
                if ((unsigned)r < 256u) {
                    #pragma unroll
                    for (int a = 0; a < 5; ++a)
                        #pragma unroll
                        for (int c = 0; c < 5; ++c)
                            bb += gk[a * 5 + c] * g[k + a][tid + c];
                }
                b[k][1 + tid] = bb;
            }
            __syncthreads();
            float e = 0.f;
            #pragma unroll
            for (int a = 0; a < 3; ++a)
                #pragma unroll
                for (int c = 0; c < 3; ++c)
                    e += sk[a * 3 + c] * b[a][tid + c];
            return e;
        };

        bool has = false;
        int firstRow = 0, lastRow = -1;
        int T_stop = -1;
        bool exhausted = true;

        __syncthreads();  // protect smem reuse after fast-path reads
        for (int i = 0; i < 256; ++i) {
            float e = compute_row(i);
            if (e != 0.f) {
                if (!has) { has = true; firstRow = i; }
                lastRow = i;
            }
            if (__syncthreads_count(has ? 0 : 1) == 0) {
                T_stop = i;
                exhausted = false;
                break;
            }
        }
        if (!exhausted && T_stop < 255) {
            bool bot = false;
            for (int i = 255; i > T_stop; --i) {
                float e = compute_row(i);
                if (e != 0.f) {
                    bot = true;
                    if (i > lastRow) lastRow = i;
                }
                if (__syncthreads_count(bot ? 0 : 1) == 0) break;
            }
        }

        int vF  = has ? firstRow : INT_MAX;
        int vL  = lastRow;
        int vMn = has ? tid : INT_MAX;
        int vMx = has ? tid : -1;
        const unsigned FULL = 0xffffffffu;
        vF  = __reduce_min_sync(FULL, vF);
        vL  = __reduce_max_sync(FULL, vL);
        vMn = __reduce_min_sync(FULL, vMn);
        vMx = __reduce_max_sync(FULL, vMx);
        int wid = tid >> 5, lane = tid & 31;
        if (lane == 0) { sF[wid] = vF; sL[wid] = vL; sMn[wid] = vMn; sMx[wid] = vMx; }
        __syncthreads();
        if (tid == 0) {
            int f = INT_MAX, l = -1, mn = INT_MAX, mx = -1;
            #pragma unroll
            for (int k = 0; k < 8; ++k) {
                f  = min(f,  sF[k]);
                l  = max(l,  sL[k]);
                mn = min(mn, sMn[k]);
                mx = max(mx, sMx[k]);
            }
            if (l >= 0) {
                atomicMax(&dstate[0], y0 + min(255, l + 2) + 1);
                atomicMax(&dstate[1], 4096 - (y0 + max(0, f - 2)));
                atomicMax(&dstate[2], x0 + min(255, mx + 2) + 1);
                atomicMax(&dstate[3], 4096 - (x0 + max(0, mn - 2)));
            }
        }
    }

    // ---------------- LAST-BLOCK FINALIZE ----------------
    if (tid == 0) {
        __threadfence();
        int prev = atomicAdd(&dstate[4], 1);
        if (prev == NBLOCKS - 1) {
            __threadfence();
            int ymaxp = dstate[0];
            if (ymaxp == 0) {
                out[0] = 0.f; out[1] = 0.f; out[2] = 0.f; out[3] = 0.f;
            } else {
                out[0] = (float)(4096 - dstate[3]);  // x_min
                out[1] = (float)(4096 - dstate[1]);  // y_min
                out[2] = (float)dstate[2];           // x_max
                out[3] = (float)ymaxp;               // y_max
            }
        }
    }
}

extern "C" void kernel_launch(void* const* d_in, const int* in_sizes, int n_in,
                              void* d_out, int out_size)
{
    const float* x     = (const float*)d_in[0];
    const float* gw    = (const float*)d_in[1];
    const float* gauss = (const float*)d_in[2];
    const float* sobel = (const float*)d_in[3];

    void* sym = nullptr;
    cudaGetSymbolAddress(&sym, dstate);
    cudaMemsetAsync(sym, 0, 5 * sizeof(int));

    tile_kernel<<<NBLOCKS, 256>>>(x, gw, gauss, sobel, (float*)d_out);
}